// round 2
// baseline (speedup 1.0000x reference)
#include <cuda_runtime.h>
#include <cuda_bf16.h>

// SpanIndexEncoder: out[t] = sum over nodes n (n < num_nodes, start_n <= t <= end_n) of emb[n]
// Strategy: difference array + hierarchical prefix scan along the token axis.
//   1. zero d_out (it doubles as the diff array)
//   2. scatter: diff[start] += emb[n]; diff[end+1] -= emb[n]   (vectorized red.global.add.v4.f32)
//   3. chunk sums (128 chunks x 64 tokens)
//   4. exclusive scan over chunk sums (single block)
//   5. apply: in-place inclusive scan within each chunk, offset by chunk prefix

#define MAX_TOKENS 8192
#define MAX_NODES  8192
#define FEAT       256
#define CHUNK      64
#define NCHUNK     (MAX_TOKENS / CHUNK)   // 128

__device__ float g_chunk[NCHUNK * FEAT];  // per-chunk feature sums -> exclusive prefixes

__device__ __forceinline__ void red_add_v4(float* p, float a, float b, float c, float d) {
    asm volatile("red.global.add.v4.f32 [%0], {%1,%2,%3,%4};"
                 :: "l"(p), "f"(a), "f"(b), "f"(c), "f"(d) : "memory");
}

// One node handled by 64 threads (64 x float4 = 256 features). 4 nodes per 256-thread block.
__global__ void __launch_bounds__(256) scatter_kernel(
    const float* __restrict__ emb,
    const int*   __restrict__ starts,
    const int*   __restrict__ ends,
    const int*   __restrict__ num_nodes_p,
    float*       __restrict__ out)
{
    const int num_nodes = num_nodes_p[0];
    const int n = blockIdx.x * 4 + (threadIdx.x >> 6);
    const int j = (threadIdx.x & 63) << 2;   // feature offset (float4 granularity)
    if (n >= num_nodes) return;
    const int s = starts[n];
    const int e = ends[n];
    if (s > e) return;                        // empty span contributes nothing

    const float4 v = *reinterpret_cast<const float4*>(emb + (size_t)n * FEAT + j);
    red_add_v4(out + (size_t)s * FEAT + j, v.x, v.y, v.z, v.w);
    if (e + 1 < MAX_TOKENS) {
        red_add_v4(out + (size_t)(e + 1) * FEAT + j, -v.x, -v.y, -v.z, -v.w);
    }
}

// One block per chunk; thread f sums its feature column over CHUNK tokens (coalesced).
__global__ void __launch_bounds__(FEAT) chunk_sum_kernel(const float* __restrict__ diff)
{
    const int c = blockIdx.x;
    const int f = threadIdx.x;
    const float* p = diff + (size_t)c * CHUNK * FEAT + f;
    float s = 0.0f;
#pragma unroll
    for (int t = 0; t < CHUNK; ++t) s += p[(size_t)t * FEAT];
    g_chunk[c * FEAT + f] = s;
}

// Single block: serial exclusive scan over the 128 chunk sums, per feature.
__global__ void __launch_bounds__(FEAT) chunk_scan_kernel()
{
    const int f = threadIdx.x;
    float run = 0.0f;
#pragma unroll
    for (int c = 0; c < NCHUNK; ++c) {
        const float v = g_chunk[c * FEAT + f];
        g_chunk[c * FEAT + f] = run;
        run += v;
    }
}

// One block per chunk: in-place inclusive scan of the diff values, seeded with chunk prefix.
__global__ void __launch_bounds__(FEAT) chunk_apply_kernel(float* __restrict__ out)
{
    const int c = blockIdx.x;
    const int f = threadIdx.x;
    float run = g_chunk[c * FEAT + f];
    float* p = out + (size_t)c * CHUNK * FEAT + f;
#pragma unroll
    for (int t = 0; t < CHUNK; ++t) {
        run += p[(size_t)t * FEAT];
        p[(size_t)t * FEAT] = run;
    }
}

extern "C" void kernel_launch(void* const* d_in, const int* in_sizes, int n_in,
                              void* d_out, int out_size)
{
    const float* emb    = (const float*)d_in[0];
    const int*   starts = (const int*)d_in[1];
    const int*   ends   = (const int*)d_in[2];
    const int*   nnp    = (const int*)d_in[3];
    float*       out    = (float*)d_out;

    // 1. zero the diff/output buffer (capturable memset node)
    cudaMemsetAsync(out, 0, (size_t)MAX_TOKENS * FEAT * sizeof(float), 0);

    // 2. scatter +emb at start, -emb at end+1
    scatter_kernel<<<MAX_NODES / 4, 256>>>(emb, starts, ends, nnp, out);

    // 3-5. hierarchical scan along tokens
    chunk_sum_kernel<<<NCHUNK, FEAT>>>(out);
    chunk_scan_kernel<<<1, FEAT>>>();
    chunk_apply_kernel<<<NCHUNK, FEAT>>>(out);
}